// round 10
// baseline (speedup 1.0000x reference)
#include <cuda_runtime.h>
#include <cuda_bf16.h>
#include <cstdint>

// Problem constants (from reference)
#define C_L0 0.05f
#define C_D  0.0075f
#define C_DS 0.005f

#define TPB 256          // batch elems per block == threads per block
#define ROWF (TPB * 14)  // floats per staged time-row (3584)
#define ROWB (ROWF * 4)  // bytes per staged time-row (14336)

// dy/ds for the 12 integrated components (r[3], R[9]); ux,uy constant.
__device__ __forceinline__ void ode_f(const float* __restrict__ y, float ux, float uy,
                                      float* __restrict__ d) {
    d[0] = y[5];
    d[1] = y[8];
    d[2] = y[11];
#pragma unroll
    for (int i = 0; i < 3; i++) {
        float r0 = y[3 + 3 * i];
        float r1 = y[4 + 3 * i];
        float r2 = y[5 + 3 * i];
        d[3 + 3 * i] = -uy * r2;
        d[4 + 3 * i] =  ux * r2;
        d[5 + 3 * i] = fmaf(uy, r0, -ux * r1);
    }
}

__device__ __forceinline__ uint32_t smem_u32(const void* p) {
    uint32_t a;
    asm("{ .reg .u64 t; cvta.to.shared.u64 t, %1; cvt.u32.u64 %0, t; }" : "=r"(a) : "l"(p));
    return a;
}

__global__ void __launch_bounds__(TPB)
ode_forward_kernel(const float* __restrict__ act, float* __restrict__ out, int B, int T) {
    // Double-buffered, output-linear staging; TMA bulk store drains each row
    // asynchronously while the next RK4 step computes.
    __shared__ __align__(128) float sbuf[2][ROWF];

    int b0 = blockIdx.x * TPB;
    int b  = b0 + threadIdx.x;
    bool active = (b < B);
    bool fullblk = (b0 + TPB <= B);
    int nvalid = min(TPB, B - b0);

    // Reference quirk: the action update at the END of loop iteration n uses
    // actions[:, n*3:(n+1)*3]; for n=0 that's columns 0:3 AGAIN. So BOTH
    // segments use actions[:, 0:3]; columns 3:6 are never consumed.
    float a0 = 0.f, a1 = 0.f, a2 = 0.f;
    if (active) {
        a0 = act[(size_t)b * 6 + 0];
        a1 = act[(size_t)b * 6 + 1];
        a2 = act[(size_t)b * 6 + 2];
    }

    float l  = C_L0 + a0;
    float ux = a2 / (-(l * C_D));
    float uy = a1 / (l * C_D);
    int length = (int)floorf(l / C_DS);
    int nsteps = min(length, T - 1);

    // y0: r=0, R=I
    float y[12];
    y[0] = 0.f; y[1] = 0.f; y[2]  = 0.f;
    y[3] = 1.f; y[4] = 0.f; y[5]  = 0.f;
    y[6] = 0.f; y[7] = 1.f; y[8]  = 0.f;
    y[9] = 0.f; y[10]= 0.f; y[11] = 1.f;

    const float h   = C_DS;
    const float h2  = 0.5f * C_DS;                 // matches f32(0.5*h)
    const float h6  = (float)(0.005 / 6.0);        // matches f32(h/6.0)

    int buf = 0;

#pragma unroll
    for (int seg = 0; seg < 2; seg++) {
        for (int t = 0; t < T; t++) {
            if (t >= 1 && t <= nsteps && active) {
                // RK4 accumulator form; summation order matches jax's
                // ((k1 + 2*k2) + 2*k3) + k4 left-assoc.
                float k[12], acc[12], yt[12];
                ode_f(y, ux, uy, k);                      // k1
#pragma unroll
                for (int j = 0; j < 12; j++) {
                    acc[j] = k[j];
                    yt[j]  = fmaf(h2, k[j], y[j]);
                }
                ode_f(yt, ux, uy, k);                     // k2
#pragma unroll
                for (int j = 0; j < 12; j++) {
                    acc[j] = fmaf(2.f, k[j], acc[j]);
                    yt[j]  = fmaf(h2, k[j], y[j]);
                }
                ode_f(yt, ux, uy, k);                     // k3
#pragma unroll
                for (int j = 0; j < 12; j++) {
                    acc[j] = fmaf(2.f, k[j], acc[j]);
                    yt[j]  = fmaf(h, k[j], y[j]);
                }
                ode_f(yt, ux, uy, k);                     // k4
#pragma unroll
                for (int j = 0; j < 12; j++) {
                    y[j] = fmaf(h6, acc[j] + k[j], y[j]);
                }
            }
            // For t > nsteps the state is frozen (== sol[min(t,length)])

            if (fullblk) {
                // Before re-staging this buffer, ensure the TMA issued 2 rows
                // ago has finished READING it (<=1 bulk group pending).
                if (threadIdx.x == 0)
                    asm volatile("cp.async.bulk.wait_group.read 1;" ::: "memory");
                __syncthreads();
            }

            // Stage in output-linear layout with float2 STS (conflict-free:
            // bank(L,j) = (L*14 + 2j) % 32 distinct within 16-lane phases).
            float2* srow = (float2*)&sbuf[buf][threadIdx.x * 14];
            if (active) {
                srow[0] = make_float2(y[0],  y[1]);
                srow[1] = make_float2(y[2],  y[3]);
                srow[2] = make_float2(y[4],  y[5]);
                srow[3] = make_float2(y[6],  y[7]);
                srow[4] = make_float2(y[8],  y[9]);
                srow[5] = make_float2(y[10], y[11]);
                srow[6] = make_float2(ux,    uy);
            }
            __syncthreads();  // all STS visible block-wide

            size_t base = ((size_t)(seg * T + t) * (size_t)B + (size_t)b0) * 14;
            if (fullblk) {
                // Single async bulk store: smem row -> gmem, 14336B, fire-and-forget.
                if (threadIdx.x == 0) {
                    asm volatile("fence.proxy.async.shared::cta;" ::: "memory");
                    asm volatile(
                        "cp.async.bulk.global.shared::cta.bulk_group [%0], [%1], %2;"
                        :: "l"(out + base), "r"(smem_u32(&sbuf[buf][0])), "r"(ROWB)
                        : "memory");
                    asm volatile("cp.async.bulk.commit_group;" ::: "memory");
                }
            } else {
                for (int f = threadIdx.x; f < nvalid * 14; f += TPB)
                    out[base + f] = sbuf[buf][f];
                __syncthreads();
            }
            buf ^= 1;
        }
    }

    // Drain all outstanding bulk stores before CTA exit.
    if (fullblk && threadIdx.x == 0)
        asm volatile("cp.async.bulk.wait_group 0;" ::: "memory");
}

extern "C" void kernel_launch(void* const* d_in, const int* in_sizes, int n_in,
                              void* d_out, int out_size) {
    const float* actions = (const float*)d_in[0];
    float* out = (float*)d_out;

    int B = in_sizes[0] / 6;                 // 262144
    int T = out_size / (2 * B * 14);         // time steps per segment (incl. t=0)

    int blocks = (B + TPB - 1) / TPB;
    ode_forward_kernel<<<blocks, TPB>>>(actions, out, B, T);
}